// round 16
// baseline (speedup 1.0000x reference)
#include <cuda_runtime.h>
#include <math.h>

#define Bsz 32
#define Rr  64
#define Ll  4096
#define Hh  768
#define NT  32          // l-tiles (Ll/128)
#define TW  128         // tile width (tokens)
#define NC  192         // float4 columns (Hh/4)

// Scratch (no device mallocs allowed)
__device__ float g_v  [Bsz * Hh];               // v[b,h] = W[h,:] . ans[b,:]
__device__ float g_T  [Bsz * NT * Hh];          // per-tile token-sum vectors (3 MB)
__device__ float g_Tp [Bsz * NT * Hh];          // cross-tile exclusive prefixes (3 MB)
__device__ float g_pre[Bsz * 2 * Rr * Hh];      // per-endpoint within-tile prefix (12.6 MB)

__device__ __forceinline__ float4 f4add(float4 a, float4 b) {
    return make_float4(a.x + b.x, a.y + b.y, a.z + b.z, a.w + b.w);
}

// ---------------------------------------------------------------------------
// Heavy kernel: grid (j=32 tiles, b=32), 192 threads (one float4 column each).
//  Phase 0: v-slice GEMV — block (j,b) computes v[b, j*24 .. j*24+24).
//           Pure producer (consumed only by k_final) -> NO inter-block sync.
//  Phase 1: build endpoint emit-lists (CSR over 128 tile positions) in smem.
//  Phase 2: stream 128 tokens (coalesced 3 KB rows, __ldcs, run-based 4-way
//           ILP); at each endpoint position emit the exclusive prefix vector
//           to g_pre; final acc -> g_T tile total.
// ---------------------------------------------------------------------------
__global__ void __launch_bounds__(192)
k_heavy(const float* __restrict__ hidden, const float* __restrict__ W,
        const float* __restrict__ ans, const int* __restrict__ span) {
    __shared__ int ep_cnt[TW];       // counts per local position
    __shared__ int ep_fill[TW];      // scatter cursors
    __shared__ int ep_off[TW + 1];   // CSR offsets
    __shared__ int ep_list[2 * Rr];  // endpoint idx, grouped by position
    __shared__ int pos_list[TW];     // sorted positions with >=1 endpoint
    __shared__ int n_pos;

    const int t    = threadIdx.x;            // 0..191, float4 column owner
    const int warp = t >> 5;                 // 0..5
    const int lane = t & 31;
    const int j    = blockIdx.x;             // tile
    const int b    = blockIdx.y;

    // ---- Phase 0: v[b, j*24 + w*4 + k] for this block's 24 rows ----------
#pragma unroll
    for (int k = 0; k < 4; k++) {
        const int h = j * 24 + warp * 4 + k;
        const float4* wrow = (const float4*)(W   + (size_t)h * Hh) + lane;
        const float4* arow = (const float4*)(ans + (size_t)b * Hh) + lane;
        float acc = 0.f;
#pragma unroll
        for (int kk = 0; kk < 6; kk++) {
            float4 w4 = wrow[kk * 32];
            float4 a4 = arow[kk * 32];
            acc += w4.x * a4.x + w4.y * a4.y + w4.z * a4.z + w4.w * a4.w;
        }
#pragma unroll
        for (int o = 16; o; o >>= 1)
            acc += __shfl_down_sync(0xffffffffu, acc, o);
        if (lane == 0)
            g_v[b * Hh + h] = acc;
    }

    // ---- Phase 1: endpoint CSR for this tile ------------------------------
    if (t < TW) { ep_cnt[t] = 0; ep_fill[t] = 0; }
    __syncthreads();

    int my_p = -1;
    if (t < 2 * Rr) {
        my_p = span[b * 2 * Rr + t];              // flat idx t = r*2+c
        if ((my_p >> 7) == j)
            atomicAdd(&ep_cnt[my_p & (TW - 1)], 1);
        else
            my_p = -1;
    }
    __syncthreads();

    if (t == 0) {
        int run = 0, m = 0;
        for (int p = 0; p < TW; p++) {
            ep_off[p] = run;
            if (ep_cnt[p] > 0) pos_list[m++] = p;
            run += ep_cnt[p];
        }
        ep_off[TW] = run;
        n_pos = m;
    }
    __syncthreads();

    if (my_p >= 0) {
        const int pl   = my_p & (TW - 1);
        const int slot = ep_off[pl] + atomicAdd(&ep_fill[pl], 1);
        ep_list[slot] = t;
    }
    __syncthreads();

    // ---- Phase 2: stream tokens, emit prefixes at endpoints ---------------
    const float4* hp = (const float4*)hidden + ((size_t)b * Ll + j * TW) * NC + t;
    float4* pre4 = (float4*)g_pre;

    float4 acc = make_float4(0.f, 0.f, 0.f, 0.f);
    int l = 0, ptr = 0;
    const int m = n_pos;

    while (l < TW) {
        const int next = (ptr < m) ? pos_list[ptr] : TW;

        // run [l, next): 4-way ILP partials
        {
            const int n = next - l;
            const float4* rp = hp + (size_t)l * NC;
            float4 p0 = make_float4(0,0,0,0), p1 = p0, p2 = p0, p3 = p0;
            int i = 0;
            for (; i + 4 <= n; i += 4) {
                p0 = f4add(p0, __ldcs(rp + (size_t)(i + 0) * NC));
                p1 = f4add(p1, __ldcs(rp + (size_t)(i + 1) * NC));
                p2 = f4add(p2, __ldcs(rp + (size_t)(i + 2) * NC));
                p3 = f4add(p3, __ldcs(rp + (size_t)(i + 3) * NC));
            }
            for (; i < n; i++)
                p0 = f4add(p0, __ldcs(rp + (size_t)i * NC));
            acc = f4add(acc, f4add(f4add(p0, p1), f4add(p2, p3)));
        }
        l = next;
        if (next < TW) {
            // emit exclusive prefix for every endpoint at this position
            for (int kk = ep_off[next]; kk < ep_off[next + 1]; kk++) {
                const int idx = ep_list[kk];
                pre4[(size_t)(b * 2 * Rr + idx) * NC + t] = acc;
            }
            ptr++;
        }
    }
    // tile total
    ((float4*)g_T)[(size_t)(b * NT + j) * NC + t] = acc;
}

// ---------------------------------------------------------------------------
// Final kernel: one block per b, 256 threads, ONLY ~3.3 KB static smem.
//  Phase 1: cross-tile exclusive prefix written to global scratch g_Tp[b]
//           (written and re-read by the SAME block; __syncthreads orders it).
//  Phase 2: csum[e]-csum[s] from g_Tp + g_pre (both L2-hot), dot with sv,
//           mask, bias, softmax.
// NOTE: rubric_mask is bool -> harness promotes to int32.
// ---------------------------------------------------------------------------
__global__ void __launch_bounds__(256)
k_final(const int* __restrict__ span,
        const int* __restrict__ mask,
        const float* __restrict__ bias,
        float* __restrict__ out) {
    __shared__ float sv[Hh];
    __shared__ float sc[Rr];

    const int b    = blockIdx.x;
    const int t    = threadIdx.x;            // 0..255
    const int warp = t >> 5;
    const int lane = t & 31;

    // ---- Phase 1: exclusive prefix over tiles -> g_Tp[b] (3 cols/thread) --
#pragma unroll
    for (int c = 0; c < 3; c++) {
        const int h = t + c * 256;
        float run = 0.f;
        for (int jj = 0; jj < NT; jj++) {
            g_Tp[(size_t)(b * NT + jj) * Hh + h] = run;
            run += g_T[(size_t)(b * NT + jj) * Hh + h];
        }
        sv[h] = g_v[b * Hh + h];
    }
    __syncthreads();     // orders this block's g_Tp writes before its reads

    // ---- Phase 2: span scores --------------------------------------------
    const float4* pre4 = (const float4*)g_pre;
    const float4* tp4  = (const float4*)g_Tp;
    const float4* sv4  = (const float4*)sv;

    for (int r = warp; r < Rr; r += 8) {
        float score;
        if (mask[b * Rr + r] == 0) {
            score = -INFINITY;
        } else {
            const int s  = span[(b * Rr + r) * 2 + 0];
            const int e  = span[(b * Rr + r) * 2 + 1];
            const int js = s >> 7, je = e >> 7;
            const float4* tcs = tp4 + (size_t)(b * NT + js) * NC;
            const float4* tce = tp4 + (size_t)(b * NT + je) * NC;
            const float4* ps  = pre4 + (size_t)(b * 2 * Rr + r * 2 + 0) * NC;
            const float4* pe  = pre4 + (size_t)(b * 2 * Rr + r * 2 + 1) * NC;
            float acc = 0.f;
#pragma unroll
            for (int k = 0; k < 6; k++) {
                const int i = lane + k * 32;
                float4 ce = f4add(tce[i], pe[i]);
                float4 cs = f4add(tcs[i], ps[i]);
                float4 vv = sv4[i];
                acc += (ce.x - cs.x) * vv.x + (ce.y - cs.y) * vv.y
                     + (ce.z - cs.z) * vv.z + (ce.w - cs.w) * vv.w;
            }
#pragma unroll
            for (int o = 16; o; o >>= 1)
                acc += __shfl_down_sync(0xffffffffu, acc, o);
            int len = e - s; if (len < 1) len = 1;
            score = acc / (float)len + bias[0];
        }
        if (lane == 0) sc[r] = score;
    }
    __syncthreads();

    if (t < 32) {
        float a0 = sc[t], a1 = sc[t + 32];
        float mx = fmaxf(a0, a1);
#pragma unroll
        for (int o = 16; o; o >>= 1)
            mx = fmaxf(mx, __shfl_xor_sync(0xffffffffu, mx, o));
        float e0 = expf(a0 - mx);
        float e1 = expf(a1 - mx);
        float ssum = e0 + e1;
#pragma unroll
        for (int o = 16; o; o >>= 1)
            ssum += __shfl_xor_sync(0xffffffffu, ssum, o);
        out[b * Rr + t]      = e0 / ssum;
        out[b * Rr + t + 32] = e1 / ssum;
    }
}

// ---------------------------------------------------------------------------
extern "C" void kernel_launch(void* const* d_in, const int* in_sizes, int n_in,
                              void* d_out, int out_size) {
    const float* ans    = (const float*)d_in[0];   // (32, 768) f32
    const float* hidden = (const float*)d_in[1];   // (32, 4096, 768) f32
    const int*   span   = (const int*)d_in[2];     // (32, 64, 2) i32
    const int*   mask   = (const int*)d_in[3];     // (32, 64) bool -> i32
    const float* W      = (const float*)d_in[4];   // (1, 768, 768) f32
    const float* bias   = (const float*)d_in[5];   // (1,) f32
    float*       out    = (float*)d_out;           // (32, 64) f32

    k_heavy<<< dim3(NT, Bsz), 192 >>> (hidden, W, ans, span);
    k_final<<< Bsz, 256 >>> (span, mask, bias, out);
}

// round 17
// speedup vs baseline: 1.2850x; 1.2850x over previous
#include <cuda_runtime.h>
#include <math.h>

#define Bsz 32
#define Rr  64
#define Ll  4096
#define Hh  768
#define NT  32          // l-tiles (Ll/128)
#define TW  128         // tile width (tokens)
#define NC  192         // float4 columns (Hh/4)

// Scratch (no device mallocs allowed)
__device__ float g_v  [Bsz * Hh];               // v[b,h] = W[h,:] . ans[b,:]
__device__ float g_T  [Bsz * NT * Hh];          // per-tile token-sum vectors (3 MB)
__device__ float g_pre[Bsz * 2 * Rr * Hh];      // per-endpoint within-tile prefix (12.6 MB)

__device__ __forceinline__ float4 f4add(float4 a, float4 b) {
    return make_float4(a.x + b.x, a.y + b.y, a.z + b.z, a.w + b.w);
}

// ---------------------------------------------------------------------------
// Heavy kernel (UNCHANGED from R16 — proven ~58us): grid (j=32, b=32),
// 192 threads (one float4 column each).
//  Phase 0: v-slice GEMV — block (j,b) computes v[b, j*24 .. j*24+24).
//  Phase 1: endpoint CSR over 128 tile positions in smem.
//  Phase 2: stream 128 tokens (coalesced 3 KB rows, __ldcs, 4-way ILP runs);
//           emit exclusive prefix vectors at endpoints; tile total -> g_T.
// ---------------------------------------------------------------------------
__global__ void __launch_bounds__(192)
k_heavy(const float* __restrict__ hidden, const float* __restrict__ W,
        const float* __restrict__ ans, const int* __restrict__ span) {
    __shared__ int ep_cnt[TW];
    __shared__ int ep_fill[TW];
    __shared__ int ep_off[TW + 1];
    __shared__ int ep_list[2 * Rr];
    __shared__ int pos_list[TW];
    __shared__ int n_pos;

    const int t    = threadIdx.x;            // 0..191
    const int warp = t >> 5;                 // 0..5
    const int lane = t & 31;
    const int j    = blockIdx.x;
    const int b    = blockIdx.y;

    // ---- Phase 0: v[b, j*24 + w*4 + k] ------------------------------------
#pragma unroll
    for (int k = 0; k < 4; k++) {
        const int h = j * 24 + warp * 4 + k;
        const float4* wrow = (const float4*)(W   + (size_t)h * Hh) + lane;
        const float4* arow = (const float4*)(ans + (size_t)b * Hh) + lane;
        float acc = 0.f;
#pragma unroll
        for (int kk = 0; kk < 6; kk++) {
            float4 w4 = wrow[kk * 32];
            float4 a4 = arow[kk * 32];
            acc += w4.x * a4.x + w4.y * a4.y + w4.z * a4.z + w4.w * a4.w;
        }
#pragma unroll
        for (int o = 16; o; o >>= 1)
            acc += __shfl_down_sync(0xffffffffu, acc, o);
        if (lane == 0)
            g_v[b * Hh + h] = acc;
    }

    // ---- Phase 1: endpoint CSR --------------------------------------------
    if (t < TW) { ep_cnt[t] = 0; ep_fill[t] = 0; }
    __syncthreads();

    int my_p = -1;
    if (t < 2 * Rr) {
        my_p = span[b * 2 * Rr + t];
        if ((my_p >> 7) == j)
            atomicAdd(&ep_cnt[my_p & (TW - 1)], 1);
        else
            my_p = -1;
    }
    __syncthreads();

    if (t == 0) {
        int run = 0, m = 0;
        for (int p = 0; p < TW; p++) {
            ep_off[p] = run;
            if (ep_cnt[p] > 0) pos_list[m++] = p;
            run += ep_cnt[p];
        }
        ep_off[TW] = run;
        n_pos = m;
    }
    __syncthreads();

    if (my_p >= 0) {
        const int pl   = my_p & (TW - 1);
        const int slot = ep_off[pl] + atomicAdd(&ep_fill[pl], 1);
        ep_list[slot] = t;
    }
    __syncthreads();

    // ---- Phase 2: stream + emit -------------------------------------------
    const float4* hp = (const float4*)hidden + ((size_t)b * Ll + j * TW) * NC + t;
    float4* pre4 = (float4*)g_pre;

    float4 acc = make_float4(0.f, 0.f, 0.f, 0.f);
    int l = 0, ptr = 0;
    const int m = n_pos;

    while (l < TW) {
        const int next = (ptr < m) ? pos_list[ptr] : TW;
        {
            const int n = next - l;
            const float4* rp = hp + (size_t)l * NC;
            float4 p0 = make_float4(0,0,0,0), p1 = p0, p2 = p0, p3 = p0;
            int i = 0;
            for (; i + 4 <= n; i += 4) {
                p0 = f4add(p0, __ldcs(rp + (size_t)(i + 0) * NC));
                p1 = f4add(p1, __ldcs(rp + (size_t)(i + 1) * NC));
                p2 = f4add(p2, __ldcs(rp + (size_t)(i + 2) * NC));
                p3 = f4add(p3, __ldcs(rp + (size_t)(i + 3) * NC));
            }
            for (; i < n; i++)
                p0 = f4add(p0, __ldcs(rp + (size_t)i * NC));
            acc = f4add(acc, f4add(f4add(p0, p1), f4add(p2, p3)));
        }
        l = next;
        if (next < TW) {
            for (int kk = ep_off[next]; kk < ep_off[next + 1]; kk++) {
                const int idx = ep_list[kk];
                pre4[(size_t)(b * 2 * Rr + idx) * NC + t] = acc;
            }
            ptr++;
        }
    }
    ((float4*)g_T)[(size_t)(b * NT + j) * NC + t] = acc;
}

// ---------------------------------------------------------------------------
// Final kernel (REWRITTEN): block per b, 512 threads, warp per span.
// Per span: csum[e]-csum[s] = sum_{jj in [js,je)} T[jj] + pre_e - pre_s.
// All loads independent (full MLP) and L2-hot. Dot with smem v, shuffle
// reduce, in-block softmax. No materialized prefix, no latency chains.
// NOTE: rubric_mask is bool -> harness promotes to int32.
// ---------------------------------------------------------------------------
__global__ void __launch_bounds__(512)
k_final(const int* __restrict__ span,
        const int* __restrict__ mask,
        const float* __restrict__ bias,
        float* __restrict__ out) {
    __shared__ float sv[Hh];
    __shared__ float sc[Rr];

    const int b    = blockIdx.x;
    const int t    = threadIdx.x;            // 0..511
    const int warp = t >> 5;                 // 0..15
    const int lane = t & 31;

    for (int i = t; i < Hh / 4; i += 512)
        ((float4*)sv)[i] = ((const float4*)(g_v + b * Hh))[i];
    __syncthreads();

    const float4* pre4 = (const float4*)g_pre;
    const float4* T4   = (const float4*)g_T;
    const float4* sv4  = (const float4*)sv;

    for (int r = warp; r < Rr; r += 16) {
        float score;
        if (mask[b * Rr + r] == 0) {
            score = -INFINITY;
        } else {
            const int s  = span[(b * Rr + r) * 2 + 0];
            const int e  = span[(b * Rr + r) * 2 + 1];
            const int js = s >> 7, je = e >> 7;
            const float4* ps = pre4 + (size_t)(b * 2 * Rr + r * 2 + 0) * NC + lane;
            const float4* pe = pre4 + (size_t)(b * 2 * Rr + r * 2 + 1) * NC + lane;

            // acc[k] = pre_e - pre_s, then += T over tiles [js, je)
            float4 a[6];
#pragma unroll
            for (int k = 0; k < 6; k++) {
                float4 ce = pe[k * 32];
                float4 cs = ps[k * 32];
                a[k] = make_float4(ce.x - cs.x, ce.y - cs.y,
                                   ce.z - cs.z, ce.w - cs.w);
            }
            for (int jj = js; jj < je; jj++) {
                const float4* tp = T4 + (size_t)(b * NT + jj) * NC + lane;
#pragma unroll
                for (int k = 0; k < 6; k++)
                    a[k] = f4add(a[k], tp[k * 32]);
            }
            float acc = 0.f;
#pragma unroll
            for (int k = 0; k < 6; k++) {
                float4 vv = sv4[lane + k * 32];
                acc += a[k].x * vv.x + a[k].y * vv.y
                     + a[k].z * vv.z + a[k].w * vv.w;
            }
#pragma unroll
            for (int o = 16; o; o >>= 1)
                acc += __shfl_down_sync(0xffffffffu, acc, o);
            int len = e - s; if (len < 1) len = 1;
            score = acc / (float)len + bias[0];
        }
        if (lane == 0) sc[r] = score;
    }
    __syncthreads();

    if (t < 32) {
        float a0 = sc[t], a1 = sc[t + 32];
        float mx = fmaxf(a0, a1);
#pragma unroll
        for (int o = 16; o; o >>= 1)
            mx = fmaxf(mx, __shfl_xor_sync(0xffffffffu, mx, o));
        float e0 = expf(a0 - mx);
        float e1 = expf(a1 - mx);
        float ssum = e0 + e1;
#pragma unroll
        for (int o = 16; o; o >>= 1)
            ssum += __shfl_xor_sync(0xffffffffu, ssum, o);
        out[b * Rr + t]      = e0 / ssum;
        out[b * Rr + t + 32] = e1 / ssum;
    }
}

// ---------------------------------------------------------------------------
extern "C" void kernel_launch(void* const* d_in, const int* in_sizes, int n_in,
                              void* d_out, int out_size) {
    const float* ans    = (const float*)d_in[0];   // (32, 768) f32
    const float* hidden = (const float*)d_in[1];   // (32, 4096, 768) f32
    const int*   span   = (const int*)d_in[2];     // (32, 64, 2) i32
    const int*   mask   = (const int*)d_in[3];     // (32, 64) bool -> i32
    const float* W      = (const float*)d_in[4];   // (1, 768, 768) f32
    const float* bias   = (const float*)d_in[5];   // (1,) f32
    float*       out    = (float*)d_out;           // (32, 64) f32

    k_heavy<<< dim3(NT, Bsz), 192 >>> (hidden, W, ans, span);
    k_final<<< Bsz, 512 >>> (span, mask, bias, out);
}